// round 7
// baseline (speedup 1.0000x reference)
#include <cuda_runtime.h>
#include <cuda_fp16.h>
#include <math.h>
#include <stdint.h>

// ===========================================================================
// PixelateDegradation:  out[b,c] = C_{t[b]} @ x0[b,c] @ C_{t[b]}^T
// mma.sync tensor path, fp16 split precision:
//   D = AhBh (fp32 acc)  +  [AhBl + AlBh] (fp16 acc, added at epilogue)
// R7: cross terms on fp16-accumulate HMMA (2x rate hypothesis); 512-thread
// CTAs, 32x32 warp tiles; inline split staging; fast weights scan.
// ===========================================================================

#define TS 20
#define SZ 256
#define NIMG 192
#define MAXT 12

__device__ float g_C[TS][SZ][SZ];
__device__ float g_tmp[(size_t)NIMG * SZ * SZ];
__device__ float g_tw[TS][SZ][MAXT];
__device__ int   g_trow[TS][SZ][MAXT];
__device__ int   g_tn[TS][SZ];

// ---------------------------------------------------------------------------
// Setup: sparse step matrices (float64 build, matches numpy)
// ---------------------------------------------------------------------------
__device__ __forceinline__ double cc1d(double x) {
    const double A = -0.75;
    return ((A + 2.0) * x - (A + 3.0)) * x * x + 1.0;
}
__device__ __forceinline__ double cc2d(double x) {
    const double A = -0.75;
    return ((A * x - 5.0 * A) * x + 8.0 * A) * x - 4.0 * A;
}

__global__ void weights_kernel() {
    int i = blockIdx.x;
    int o = threadIdx.x;
    __shared__ float sw[SZ][4];
    __shared__ int   scol[SZ][4];

    double s = (double)(SZ - i);
    int src = (int)floor((o + 0.5) * s / 256.0);
    int smax = (SZ - i) - 1;
    if (src > smax) src = smax;
    if (src < 0) src = 0;

    double x  = (src + 0.5) * 256.0 / s - 0.5;
    double i0 = floor(x);
    double tt = x - i0;
    double ws[4] = {cc2d(tt + 1.0), cc1d(tt), cc1d(1.0 - tt), cc2d(2.0 - tt)};
    int ib = (int)i0;
#pragma unroll
    for (int k = 0; k < 4; k++) {
        int c = ib - 1 + k;
        if (c < 0) c = 0;
        if (c > SZ - 1) c = SZ - 1;
        scol[o][k] = c;
        sw[o][k]   = (float)ws[k];
    }
    __syncthreads();

    // transpose via windowed scan: taps land within |r - h| <= ~6; use +-12.
    int h = threadIdx.x;
    int r_lo = h - 12; if (r_lo < 0) r_lo = 0;
    int r_hi = h + 12; if (r_hi > SZ - 1) r_hi = SZ - 1;
    int cnt = 0;
    for (int r = r_lo; r <= r_hi; r++) {
#pragma unroll
        for (int k = 0; k < 4; k++) {
            if (scol[r][k] == h && cnt < MAXT) {
                g_trow[i][h][cnt] = r;
                g_tw[i][h][cnt]   = sw[r][k];
                cnt++;
            }
        }
    }
    g_tn[i][h] = cnt;
}

// prefix products C_t (fp32)
__global__ void chain_kernel() {
    int o = blockIdx.x;
    int t = blockIdx.y;
    int h = threadIdx.x;

    __shared__ float u[SZ];
    u[h] = (h == o) ? 1.0f : 0.0f;
    __syncthreads();

    for (int step = t - 1; step >= 0; --step) {
        int n = g_tn[step][h];
        float acc = 0.0f;
        for (int j = 0; j < n; j++)
            acc += g_tw[step][h][j] * u[g_trow[step][h][j]];
        __syncthreads();
        u[h] = acc;
        __syncthreads();
    }
    g_C[t][o][h] = u[h];
}

// ---------------------------------------------------------------------------
// GEMM: 128x128 CTA tile, 512 threads (16 warps, 32x32 warp tiles),
// K-chunk 32, double-buffered smem. Per-buffer layout (80B row pitch):
// Ah +0, Al +10240, Bh +20480, Bl +30720; buffer stride 40960; total 81920.
// ---------------------------------------------------------------------------
static constexpr int SMEM_BYTES = 81920;
static constexpr uint32_t T_AL = 10240;
static constexpr uint32_t T_BH = 20480;
static constexpr uint32_t BUFSTRIDE = 40960;

__device__ __forceinline__ uint32_t smem_to_u32(const void* p) {
    uint32_t a;
    asm("{ .reg .u64 t; cvta.to.shared.u64 t, %1; cvt.u32.u64 %0, t; }"
        : "=r"(a) : "l"(p));
    return a;
}
__device__ __forceinline__ void ldsm_x4(uint32_t r[4], uint32_t addr) {
    asm volatile("ldmatrix.sync.aligned.m8n8.x4.shared.b16 {%0,%1,%2,%3}, [%4];"
                 : "=r"(r[0]), "=r"(r[1]), "=r"(r[2]), "=r"(r[3]) : "r"(addr));
}
// fp32-accumulate HMMA (main term)
__device__ __forceinline__ void mma_f32(float d[4], const uint32_t a[4],
                                        const uint32_t b[2]) {
    asm volatile(
        "mma.sync.aligned.m16n8k16.row.col.f32.f16.f16.f32 "
        "{%0,%1,%2,%3}, {%4,%5,%6,%7}, {%8,%9}, {%0,%1,%2,%3};"
        : "+f"(d[0]), "+f"(d[1]), "+f"(d[2]), "+f"(d[3])
        : "r"(a[0]), "r"(a[1]), "r"(a[2]), "r"(a[3]), "r"(b[0]), "r"(b[1]));
}
// fp16-accumulate HMMA (cross terms; values ~2^-11, precision ample)
__device__ __forceinline__ void mma_f16(uint32_t c[2], const uint32_t a[4],
                                        const uint32_t b[2]) {
    asm volatile(
        "mma.sync.aligned.m16n8k16.row.col.f16.f16.f16.f16 "
        "{%0,%1}, {%2,%3,%4,%5}, {%6,%7}, {%0,%1};"
        : "+r"(c[0]), "+r"(c[1])
        : "r"(a[0]), "r"(a[1]), "r"(a[2]), "r"(a[3]), "r"(b[0]), "r"(b[1]));
}

#define STS128(r0, r1, r2, r3, addr) \
    asm volatile("st.shared.v4.b32 [%0], {%1, %2, %3, %4};" \
        :: "r"(addr), "r"(r0), "r"(r1), "r"(r2), "r"(r3) : "memory")

__device__ __forceinline__ void split_pack8(const float v[8], uint32_t hi[4],
                                            uint32_t lo[4]) {
#pragma unroll
    for (int i = 0; i < 4; i++) {
        float a = v[2 * i], b = v[2 * i + 1];
        __half ha = __float2half_rn(a), hb = __float2half_rn(b);
        __half la = __float2half_rn(a - __half2float(ha));
        __half lb = __float2half_rn(b - __half2float(hb));
        __half2 h = __halves2half2(ha, hb);
        __half2 l = __halves2half2(la, lb);
        hi[i] = *reinterpret_cast<const uint32_t*>(&h);
        lo[i] = *reinterpret_cast<const uint32_t*>(&l);
    }
}

// stage 8 consecutive fp32 -> hi/lo fp16 at tile row `row`, 16B chunk s.
__device__ __forceinline__ void stage8(uint32_t hiBase, int row, int s,
                                       const float* __restrict__ src8) {
    const float4* p4 = reinterpret_cast<const float4*>(src8);
    float4 a = p4[0], b = p4[1];
    float v[8] = {a.x, a.y, a.z, a.w, b.x, b.y, b.z, b.w};
    uint32_t hi[4], lo[4];
    split_pack8(v, hi, lo);
    uint32_t addr = hiBase + (uint32_t)(row * 80 + s * 16);
    STS128(hi[0], hi[1], hi[2], hi[3], addr);
    STS128(lo[0], lo[1], lo[2], lo[3], addr + T_AL);
}

// D[mb:mb+128, nb:nb+128] = A[128,256] @ op(B); BT: B[n][k] = Bg[k][n]
template <bool BT>
__device__ __forceinline__ void mm_core(const float* __restrict__ Ag,
                                        const float* __restrict__ Bg,
                                        float* __restrict__ Dg) {
    extern __shared__ char smem[];
    uint32_t sb = smem_to_u32(smem);

    const int tid   = threadIdx.x;
    const int lane  = tid & 31;
    const int wid   = tid >> 5;          // 0..15
    const int warpm = wid & 3;           // 4 m-groups of 32 rows
    const int warpn = wid >> 2;          // 4 n-groups of 32 cols
    const int mb    = blockIdx.y * 128;
    const int nb    = blockIdx.x * 128;

    float    accF[2][4][4];
    uint32_t accH[2][4][2];
#pragma unroll
    for (int i = 0; i < 2; i++)
#pragma unroll
        for (int j = 0; j < 4; j++) {
#pragma unroll
            for (int q = 0; q < 4; q++) accF[i][j][q] = 0.0f;
            accH[i][j][0] = 0u;
            accH[i][j][1] = 0u;
        }

    const uint32_t arow0 = sb +
        (uint32_t)((warpm * 32 + (lane & 15)) * 80 + ((lane & 16) ? 16 : 0));
    const uint32_t brow0 = sb + T_BH +
        (uint32_t)((warpn * 32 + (lane & 7) + ((lane & 16) ? 8 : 0)) * 80 +
                   ((lane & 8) ? 16 : 0));

#pragma unroll 1
    for (int c = 0; c < 8; c++) {
        const int kc = c * 32;
        const uint32_t buf = (uint32_t)((c & 1) * BUFSTRIDE);

        // ---- stage A (128 rows x 32 k, k-contig) : 1 stage8 per thread ----
        {
            int r = tid >> 2, s = tid & 3;
            stage8(sb + buf, r, s, Ag + (size_t)(mb + r) * SZ + kc + s * 8);
        }
        // ---- stage B (128 n-rows x 32 k) ----
        if (!BT) {
            int r = tid >> 2, s = tid & 3;
            stage8(sb + buf + T_BH, r, s,
                   Bg + (size_t)(nb + r) * SZ + kc + s * 8);
        } else {
            int n0 = (wid & 3) * 32;
            int j0 = (wid >> 2) * 8;
            const float* xp = Bg + (size_t)(kc + j0) * SZ + nb + n0 + lane;
            float v[8];
#pragma unroll
            for (int j = 0; j < 8; j++) v[j] = xp[(size_t)j * SZ];
            uint32_t hi[4], lo[4];
            split_pack8(v, hi, lo);
            uint32_t addr = sb + buf + T_BH +
                (uint32_t)((n0 + lane) * 80 + (j0 >> 3) * 16);
            STS128(hi[0], hi[1], hi[2], hi[3], addr);
            STS128(lo[0], lo[1], lo[2], lo[3], addr + T_AL);
        }
        __syncthreads();

        // ---- compute ----
#pragma unroll
        for (int K16 = 0; K16 < 2; K16++) {
            uint32_t aH[2][4], aL[2][4];
#pragma unroll
            for (int mt = 0; mt < 2; mt++) {
                uint32_t a = arow0 + buf + (uint32_t)(mt * 16 * 80 + K16 * 32);
                ldsm_x4(aH[mt], a);
                ldsm_x4(aL[mt], a + T_AL);
            }
            uint32_t bH[2][4], bL[2][4];
#pragma unroll
            for (int g = 0; g < 2; g++) {
                uint32_t b = brow0 + buf + (uint32_t)(g * 16 * 80 + K16 * 32);
                ldsm_x4(bH[g], b);
                ldsm_x4(bL[g], b + T_AL);
            }
            // main term: fp32 accumulate
#pragma unroll
            for (int g = 0; g < 2; g++)
#pragma unroll
                for (int mt = 0; mt < 2; mt++) {
                    mma_f32(accF[mt][2 * g],     aH[mt], bH[g]);
                    mma_f32(accF[mt][2 * g + 1], aH[mt], bH[g] + 2);
                }
            // cross terms: fp16 accumulate
#pragma unroll
            for (int g = 0; g < 2; g++)
#pragma unroll
                for (int mt = 0; mt < 2; mt++) {
                    mma_f16(accH[mt][2 * g],     aH[mt], bL[g]);
                    mma_f16(accH[mt][2 * g + 1], aH[mt], bL[g] + 2);
                }
#pragma unroll
            for (int g = 0; g < 2; g++)
#pragma unroll
                for (int mt = 0; mt < 2; mt++) {
                    mma_f16(accH[mt][2 * g],     aL[mt], bH[g]);
                    mma_f16(accH[mt][2 * g + 1], aL[mt], bH[g] + 2);
                }
        }
        __syncthreads();
    }

    // ---- epilogue: D = accF + float(accH) ----
    const int rbase = mb + warpm * 32 + (lane >> 2);
    const int cbase = nb + warpn * 32 + (lane & 3) * 2;
#pragma unroll
    for (int mt = 0; mt < 2; mt++) {
#pragma unroll
        for (int nt = 0; nt < 4; nt++) {
            int col = cbase + nt * 8;
            int r0 = rbase + mt * 16;
            int r1 = r0 + 8;
            __half2 x0h = *reinterpret_cast<__half2*>(&accH[mt][nt][0]);
            __half2 x1h = *reinterpret_cast<__half2*>(&accH[mt][nt][1]);
            float v0 = accF[mt][nt][0] + __low2float(x0h);
            float v1 = accF[mt][nt][1] + __high2float(x0h);
            float v2 = accF[mt][nt][2] + __low2float(x1h);
            float v3 = accF[mt][nt][3] + __high2float(x1h);
            *reinterpret_cast<float2*>(Dg + (size_t)r0 * SZ + col) =
                make_float2(v0, v1);
            *reinterpret_cast<float2*>(Dg + (size_t)r1 * SZ + col) =
                make_float2(v2, v3);
        }
    }
}

__global__ void __launch_bounds__(512, 1)
phase1_kernel(const float* __restrict__ x0, const int* __restrict__ t) {
    int img = blockIdx.z;
    int tb  = __ldg(&t[img / 3]);
    mm_core<true>(&g_C[tb][0][0], x0 + (size_t)img * SZ * SZ,
                  g_tmp + (size_t)img * SZ * SZ);
}

__global__ void __launch_bounds__(512, 1)
phase2_kernel(float* __restrict__ out, const int* __restrict__ t) {
    int img = blockIdx.z;
    int tb  = __ldg(&t[img / 3]);
    mm_core<false>(g_tmp + (size_t)img * SZ * SZ, &g_C[tb][0][0],
                   out + (size_t)img * SZ * SZ);
}

// ---------------------------------------------------------------------------
extern "C" void kernel_launch(void* const* d_in, const int* in_sizes, int n_in,
                              void* d_out, int out_size) {
    const float* x0 = (const float*)d_in[0];
    const int*   t  = (const int*)d_in[1];
    float* out      = (float*)d_out;

    weights_kernel<<<TS, 256>>>();
    chain_kernel<<<dim3(SZ, TS), 256>>>();

    cudaFuncSetAttribute(phase1_kernel,
                         cudaFuncAttributeMaxDynamicSharedMemorySize, SMEM_BYTES);
    cudaFuncSetAttribute(phase2_kernel,
                         cudaFuncAttributeMaxDynamicSharedMemorySize, SMEM_BYTES);
    phase1_kernel<<<dim3(2, 2, NIMG), 512, SMEM_BYTES>>>(x0, t);
    phase2_kernel<<<dim3(2, 2, NIMG), 512, SMEM_BYTES>>>(out, t);
}

// round 8
// speedup vs baseline: 1.4148x; 1.4148x over previous
#include <cuda_runtime.h>
#include <cuda_fp16.h>
#include <math.h>
#include <stdint.h>

// ===========================================================================
// PixelateDegradation:  out[b,c] = C_{t[b]} @ x0[b,c] @ C_{t[b]}^T
// mma.sync tensor path, 2-term fp16 split:  D = (Ah + Al) @ Bh
//  (A exact via hi+lo split, B rounded once to fp16; err ~2^-12/GEMM)
// ===========================================================================

#define TS 20
#define SZ 256
#define NIMG 192
#define MAXT 12

__device__ __half g_Ch[TS][SZ][SZ];
__device__ __half g_Cl[TS][SZ][SZ];
__device__ __half g_Yh[(size_t)NIMG * SZ * SZ];   // Y = C@X hi (m-major, k-contig)
__device__ __half g_Yl[(size_t)NIMG * SZ * SZ];   // Y lo
__device__ float g_tw[TS][SZ][MAXT];
__device__ int   g_trow[TS][SZ][MAXT];
__device__ int   g_tn[TS][SZ];

// ---------------------------------------------------------------------------
// Setup: sparse step matrices (float64 build, matches numpy)
// ---------------------------------------------------------------------------
__device__ __forceinline__ double cc1d(double x) {
    const double A = -0.75;
    return ((A + 2.0) * x - (A + 3.0)) * x * x + 1.0;
}
__device__ __forceinline__ double cc2d(double x) {
    const double A = -0.75;
    return ((A * x - 5.0 * A) * x + 8.0 * A) * x - 4.0 * A;
}

__global__ void weights_kernel() {
    int i = blockIdx.x;
    int o = threadIdx.x;
    __shared__ float sw[SZ][4];
    __shared__ int   scol[SZ][4];

    double s = (double)(SZ - i);
    int src = (int)floor((o + 0.5) * s / 256.0);
    int smax = (SZ - i) - 1;
    if (src > smax) src = smax;
    if (src < 0) src = 0;

    double x  = (src + 0.5) * 256.0 / s - 0.5;
    double i0 = floor(x);
    double tt = x - i0;
    double ws[4] = {cc2d(tt + 1.0), cc1d(tt), cc1d(1.0 - tt), cc2d(2.0 - tt)};
    int ib = (int)i0;
#pragma unroll
    for (int k = 0; k < 4; k++) {
        int c = ib - 1 + k;
        if (c < 0) c = 0;
        if (c > SZ - 1) c = SZ - 1;
        scol[o][k] = c;
        sw[o][k]   = (float)ws[k];
    }
    __syncthreads();

    // transpose via windowed scan: taps land within |r - h| <= ~6; use +-12.
    int h = threadIdx.x;
    int r_lo = h - 12; if (r_lo < 0) r_lo = 0;
    int r_hi = h + 12; if (r_hi > SZ - 1) r_hi = SZ - 1;
    int cnt = 0;
    for (int r = r_lo; r <= r_hi; r++) {
#pragma unroll
        for (int k = 0; k < 4; k++) {
            if (scol[r][k] == h && cnt < MAXT) {
                g_trow[i][h][cnt] = r;
                g_tw[i][h][cnt]   = sw[r][k];
                cnt++;
            }
        }
    }
    g_tn[i][h] = cnt;
}

// prefix products C_t, ping-pong buffer (1 barrier/step), split hi/lo output
__global__ void chain_kernel() {
    int o = blockIdx.x;
    int t = blockIdx.y;
    int h = threadIdx.x;

    __shared__ float u[2][SZ];
    u[0][h] = (h == o) ? 1.0f : 0.0f;
    __syncthreads();

    int cur = 0;
    for (int step = t - 1; step >= 0; --step) {
        int n = g_tn[step][h];
        float acc = 0.0f;
        for (int j = 0; j < n; j++)
            acc += g_tw[step][h][j] * u[cur][g_trow[step][h][j]];
        u[cur ^ 1][h] = acc;
        cur ^= 1;
        __syncthreads();
    }
    float v = u[cur][h];
    __half hv = __float2half_rn(v);
    __half lv = __float2half_rn(v - __half2float(hv));
    g_Ch[t][o][h] = hv;
    g_Cl[t][o][h] = lv;
}

// ---------------------------------------------------------------------------
// GEMM: 128x128 CTA tile, 8 warps (32x64 warp tiles), K-chunk 32,
// double-buffered smem. Per-buffer layout (80B row pitch):
//   Ah +0 (8KB pitched=10240), Al +10240, Bh +20480 ; stride 30720 ; x2.
// ---------------------------------------------------------------------------
static constexpr int SMEM_BYTES = 61440;
static constexpr uint32_t T_AL = 10240;
static constexpr uint32_t T_B  = 20480;
static constexpr uint32_t BUFSTRIDE = 30720;

__device__ __forceinline__ uint32_t smem_to_u32(const void* p) {
    uint32_t a;
    asm("{ .reg .u64 t; cvta.to.shared.u64 t, %1; cvt.u32.u64 %0, t; }"
        : "=r"(a) : "l"(p));
    return a;
}
__device__ __forceinline__ void ldsm_x4(uint32_t r[4], uint32_t addr) {
    asm volatile("ldmatrix.sync.aligned.m8n8.x4.shared.b16 {%0,%1,%2,%3}, [%4];"
                 : "=r"(r[0]), "=r"(r[1]), "=r"(r[2]), "=r"(r[3]) : "r"(addr));
}
__device__ __forceinline__ void mma16816(float d[4], const uint32_t a[4],
                                         const uint32_t b[2]) {
    asm volatile(
        "mma.sync.aligned.m16n8k16.row.col.f32.f16.f16.f32 "
        "{%0,%1,%2,%3}, {%4,%5,%6,%7}, {%8,%9}, {%0,%1,%2,%3};"
        : "+f"(d[0]), "+f"(d[1]), "+f"(d[2]), "+f"(d[3])
        : "r"(a[0]), "r"(a[1]), "r"(a[2]), "r"(a[3]), "r"(b[0]), "r"(b[1]));
}
__device__ __forceinline__ void cp16(uint32_t d, const void* g) {
    asm volatile("cp.async.cg.shared.global [%0], [%1], 16;"
                 :: "r"(d), "l"(g) : "memory");
}
#define CP_COMMIT() asm volatile("cp.async.commit_group;" ::: "memory")
#define CP_WAIT(N)  asm volatile("cp.async.wait_group %0;" :: "n"(N) : "memory")

#define STS128(r0, r1, r2, r3, addr) \
    asm volatile("st.shared.v4.b32 [%0], {%1, %2, %3, %4};" \
        :: "r"(addr), "r"(r0), "r"(r1), "r"(r2), "r"(r3) : "memory")

// pack 8 floats to fp16 hi only
__device__ __forceinline__ void pack8_hi(const float v[8], uint32_t hi[4]) {
#pragma unroll
    for (int i = 0; i < 4; i++) {
        __half2 h = __halves2half2(__float2half_rn(v[2 * i]),
                                   __float2half_rn(v[2 * i + 1]));
        hi[i] = *reinterpret_cast<const uint32_t*>(&h);
    }
}

// stage A tile (128 rows x 32 k) hi+lo from pre-split gmem via cp.async
__device__ __forceinline__ void stageA_cp(uint32_t buf,
                                          const __half* __restrict__ Ah,
                                          const __half* __restrict__ Al,
                                          int mb, int kc, int tid) {
    int r = tid >> 1;                 // 0..127
    int s = (tid & 1) * 2;            // chunk 0 or 2
    uint32_t dst = buf + (uint32_t)(r * 80 + s * 16);
    size_t goff = (size_t)(mb + r) * SZ + kc + s * 8;
    cp16(dst,               Ah + goff);
    cp16(dst + 16,          Ah + goff + 8);
    cp16(dst + T_AL,        Al + goff);
    cp16(dst + T_AL + 16,   Al + goff + 8);
}

// stage B tile (128 n-rows x 32 k) hi-only from pre-split gmem via cp.async
__device__ __forceinline__ void stageB_cp(uint32_t buf,
                                          const __half* __restrict__ Bh,
                                          int nb, int kc, int tid) {
    int r = tid >> 1;
    int s = (tid & 1) * 2;
    uint32_t dst = buf + T_B + (uint32_t)(r * 80 + s * 16);
    size_t goff = (size_t)(nb + r) * SZ + kc + s * 8;
    cp16(dst,      Bh + goff);
    cp16(dst + 16, Bh + goff + 8);
}

// stage B tile from fp32 X with transpose: B[n][k] = X[kc+k][nb+n], hi-only
__device__ __forceinline__ void stageB_trans(uint32_t buf,
                                             const float* __restrict__ X,
                                             int nb, int kc, int wid, int lane) {
#pragma unroll
    for (int rep = 0; rep < 2; rep++) {
        int it = wid + rep * 8;        // 16 tasks
        int j0 = (it & 3) * 8;         // k-group of 8
        int n0 = (it >> 2) * 32;       // n-group of 32
        const float* xp = X + (size_t)(kc + j0) * SZ + nb + n0 + lane;
        float v[8];
#pragma unroll
        for (int j = 0; j < 8; j++) v[j] = xp[(size_t)j * SZ];
        uint32_t hi[4];
        pack8_hi(v, hi);
        uint32_t addr = buf + T_B +
            (uint32_t)((n0 + lane) * 80 + (j0 >> 3) * 16);
        STS128(hi[0], hi[1], hi[2], hi[3], addr);
    }
}

__device__ __forceinline__ void compute_chunk(uint32_t buf, int warpm, int warpn,
                                              int lane, float acc[2][8][4]) {
    const uint32_t arow = buf +
        (uint32_t)((warpm * 32 + (lane & 15)) * 80 + ((lane & 16) ? 16 : 0));
    const uint32_t brow = buf + T_B +
        (uint32_t)((warpn * 64 + (lane & 7) + ((lane & 16) ? 8 : 0)) * 80 +
                   ((lane & 8) ? 16 : 0));
#pragma unroll
    for (int K16 = 0; K16 < 2; K16++) {
        uint32_t aH[2][4], aL[2][4];
#pragma unroll
        for (int mt = 0; mt < 2; mt++) {
            uint32_t a = arow + (uint32_t)(mt * 16 * 80 + K16 * 32);
            ldsm_x4(aH[mt], a);
            ldsm_x4(aL[mt], a + T_AL);
        }
        uint32_t bH[4][4];
#pragma unroll
        for (int g = 0; g < 4; g++)
            ldsm_x4(bH[g], brow + (uint32_t)(g * 16 * 80 + K16 * 32));
        // term-major ordering: all Ah mmas, then all Al mmas (long RAW gaps)
#pragma unroll
        for (int g = 0; g < 4; g++)
#pragma unroll
            for (int mt = 0; mt < 2; mt++) {
                mma16816(acc[mt][2 * g],     aH[mt], bH[g]);
                mma16816(acc[mt][2 * g + 1], aH[mt], bH[g] + 2);
            }
#pragma unroll
        for (int g = 0; g < 4; g++)
#pragma unroll
            for (int mt = 0; mt < 2; mt++) {
                mma16816(acc[mt][2 * g],     aL[mt], bH[g]);
                mma16816(acc[mt][2 * g + 1], aL[mt], bH[g] + 2);
            }
    }
}

// PH1: A = C split (cp.async), B = X transposed inline; epilogue splits Y.
// PH2: A = Y split (cp.async), B = Ch (cp.async); epilogue fp32.
template <bool PH1>
__device__ __forceinline__ void mm_core(
    const __half* __restrict__ Ah, const __half* __restrict__ Al,
    const __half* __restrict__ Bh, const float* __restrict__ Xf,
    float* __restrict__ Of, __half* __restrict__ Oh, __half* __restrict__ Ol) {
    extern __shared__ char smem[];
    uint32_t sb = smem_to_u32(smem);

    const int tid   = threadIdx.x;
    const int lane  = tid & 31;
    const int wid   = tid >> 5;
    const int warpm = wid & 3;      // 4 m-tiles of 32
    const int warpn = wid >> 2;     // 2 n-tiles of 64
    const int mb    = blockIdx.y * 128;
    const int nb    = blockIdx.x * 128;

    float acc[2][8][4];
#pragma unroll
    for (int i = 0; i < 2; i++)
#pragma unroll
        for (int j = 0; j < 8; j++)
#pragma unroll
            for (int q = 0; q < 4; q++) acc[i][j][q] = 0.0f;

    // prologue: stage chunk 0
    stageA_cp(sb, Ah, Al, mb, 0, tid);
    if (PH1) stageB_trans(sb, Xf, nb, 0, wid, lane);
    else     stageB_cp(sb, Bh, nb, 0, tid);
    CP_COMMIT();
    // stage chunk 1
    stageA_cp(sb + BUFSTRIDE, Ah, Al, mb, 32, tid);
    if (PH1) stageB_trans(sb + BUFSTRIDE, Xf, nb, 32, wid, lane);
    else     stageB_cp(sb + BUFSTRIDE, Bh, nb, 32, tid);
    CP_COMMIT();

#pragma unroll 1
    for (int c = 0; c < 8; c++) {
        if (c < 7) { CP_WAIT(1); } else { CP_WAIT(0); }
        __syncthreads();
        uint32_t buf = sb + (uint32_t)((c & 1) * BUFSTRIDE);
        compute_chunk(buf, warpm, warpn, lane, acc);
        __syncthreads();
        if (c + 2 < 8) {
            stageA_cp(buf, Ah, Al, mb, (c + 2) * 32, tid);
            if (PH1) stageB_trans(buf, Xf, nb, (c + 2) * 32, wid, lane);
            else     stageB_cp(buf, Bh, nb, (c + 2) * 32, tid);
            CP_COMMIT();
        }
    }

    // epilogue
    const int rbase = mb + warpm * 32 + (lane >> 2);
    const int cbase = nb + warpn * 64 + (lane & 3) * 2;
#pragma unroll
    for (int mt = 0; mt < 2; mt++) {
#pragma unroll
        for (int nt = 0; nt < 8; nt++) {
            int col = cbase + nt * 8;
            int r0 = rbase + mt * 16;
            int r1 = r0 + 8;
            float v0 = acc[mt][nt][0], v1 = acc[mt][nt][1];
            float v2 = acc[mt][nt][2], v3 = acc[mt][nt][3];
            if (PH1) {
                __half h0 = __float2half_rn(v0), h1 = __float2half_rn(v1);
                __half h2 = __float2half_rn(v2), h3 = __float2half_rn(v3);
                __half l0 = __float2half_rn(v0 - __half2float(h0));
                __half l1 = __float2half_rn(v1 - __half2float(h1));
                __half l2 = __float2half_rn(v2 - __half2float(h2));
                __half l3 = __float2half_rn(v3 - __half2float(h3));
                *reinterpret_cast<__half2*>(Oh + (size_t)r0 * SZ + col) =
                    __halves2half2(h0, h1);
                *reinterpret_cast<__half2*>(Ol + (size_t)r0 * SZ + col) =
                    __halves2half2(l0, l1);
                *reinterpret_cast<__half2*>(Oh + (size_t)r1 * SZ + col) =
                    __halves2half2(h2, h3);
                *reinterpret_cast<__half2*>(Ol + (size_t)r1 * SZ + col) =
                    __halves2half2(l2, l3);
            } else {
                *reinterpret_cast<float2*>(Of + (size_t)r0 * SZ + col) =
                    make_float2(v0, v1);
                *reinterpret_cast<float2*>(Of + (size_t)r1 * SZ + col) =
                    make_float2(v2, v3);
            }
        }
    }
}

__global__ void __launch_bounds__(256, 2)
phase1_kernel(const float* __restrict__ x0, const int* __restrict__ t) {
    int img = blockIdx.z;
    int tb  = __ldg(&t[img / 3]);
    size_t io = (size_t)img * SZ * SZ;
    mm_core<true>(&g_Ch[tb][0][0], &g_Cl[tb][0][0], nullptr,
                  x0 + io, nullptr, g_Yh + io, g_Yl + io);
}

__global__ void __launch_bounds__(256, 2)
phase2_kernel(float* __restrict__ out, const int* __restrict__ t) {
    int img = blockIdx.z;
    int tb  = __ldg(&t[img / 3]);
    size_t io = (size_t)img * SZ * SZ;
    mm_core<false>(g_Yh + io, g_Yl + io, &g_Ch[tb][0][0],
                   nullptr, out + io, nullptr, nullptr);
}

// ---------------------------------------------------------------------------
extern "C" void kernel_launch(void* const* d_in, const int* in_sizes, int n_in,
                              void* d_out, int out_size) {
    const float* x0 = (const float*)d_in[0];
    const int*   t  = (const int*)d_in[1];
    float* out      = (float*)d_out;

    weights_kernel<<<TS, 256>>>();
    chain_kernel<<<dim3(SZ, TS), 256>>>();

    cudaFuncSetAttribute(phase1_kernel,
                         cudaFuncAttributeMaxDynamicSharedMemorySize, SMEM_BYTES);
    cudaFuncSetAttribute(phase2_kernel,
                         cudaFuncAttributeMaxDynamicSharedMemorySize, SMEM_BYTES);
    phase1_kernel<<<dim3(2, 2, NIMG), 256, SMEM_BYTES>>>(x0, t);
    phase2_kernel<<<dim3(2, 2, NIMG), 256, SMEM_BYTES>>>(out, t);
}

// round 9
// speedup vs baseline: 1.8448x; 1.3040x over previous
#include <cuda_runtime.h>
#include <cuda_fp16.h>
#include <math.h>
#include <stdint.h>

// ===========================================================================
// PixelateDegradation:  out[b,c] = C_{t[b]} @ x0[b,c] @ C_{t[b]}^T
// mma.sync tensor path, 2-term fp16 split:  D = (Ah + Al) @ Bh
// R9: single-pass chain kernel (C_{s+1} col = M_s * C_s col, taps computed
// on the fly in fp64); weights kernel + tap globals removed.
// ===========================================================================

#define TS 20
#define SZ 256
#define NIMG 192

__device__ __half g_Ch[TS][SZ][SZ];
__device__ __half g_Cl[TS][SZ][SZ];
__device__ __half g_Yh[(size_t)NIMG * SZ * SZ];   // Y = C@X hi (m-major, k-contig)
__device__ __half g_Yl[(size_t)NIMG * SZ * SZ];   // Y lo

// ---------------------------------------------------------------------------
// Chain kernel: block = 4 columns of C, thread = row o. 20 sequential steps.
// c_{s+1}[o] = sum_k w_k(o,s) * c_s[scol_k(o,s)]   (row-major bicubic taps,
// computed per step in double to match the numpy float64 build).
// ---------------------------------------------------------------------------
__device__ __forceinline__ double cc1d(double x) {
    const double A = -0.75;
    return ((A + 2.0) * x - (A + 3.0)) * x * x + 1.0;
}
__device__ __forceinline__ double cc2d(double x) {
    const double A = -0.75;
    return ((A * x - 5.0 * A) * x + 8.0 * A) * x - 4.0 * A;
}

__global__ void chain_kernel() {
    const int o  = threadIdx.x;
    const int h0 = blockIdx.x * 4;

    __shared__ float c[2][SZ][4];
#pragma unroll
    for (int j = 0; j < 4; j++)
        c[0][o][j] = (o == h0 + j) ? 1.0f : 0.0f;
    __syncthreads();

    int cur = 0;
#pragma unroll 1
    for (int s = 0; s < TS; s++) {
        // store C_s column slice (own row of shared -> no sync needed)
        float4 v = *reinterpret_cast<const float4*>(&c[cur][o][0]);
        __half hx = __float2half_rn(v.x), hy = __float2half_rn(v.y);
        __half hz = __float2half_rn(v.z), hw = __float2half_rn(v.w);
        __half lx = __float2half_rn(v.x - __half2float(hx));
        __half ly = __float2half_rn(v.y - __half2float(hy));
        __half lz = __float2half_rn(v.z - __half2float(hz));
        __half lw = __float2half_rn(v.w - __half2float(hw));
        uint2 hs, ls;
        __half2 t0 = __halves2half2(hx, hy), t1 = __halves2half2(hz, hw);
        hs.x = *reinterpret_cast<uint32_t*>(&t0);
        hs.y = *reinterpret_cast<uint32_t*>(&t1);
        __half2 t2 = __halves2half2(lx, ly), t3 = __halves2half2(lz, lw);
        ls.x = *reinterpret_cast<uint32_t*>(&t2);
        ls.y = *reinterpret_cast<uint32_t*>(&t3);
        *reinterpret_cast<uint2*>(&g_Ch[s][o][h0]) = hs;
        *reinterpret_cast<uint2*>(&g_Cl[s][o][h0]) = ls;

        if (s == TS - 1) break;

        // taps of M_s at output row o (double, matches numpy)
        double ss = (double)(SZ - s);
        int src = (int)floor((o + 0.5) * ss / 256.0);
        int smax = (SZ - s) - 1;
        if (src > smax) src = smax;
        if (src < 0) src = 0;
        double x  = (src + 0.5) * 256.0 / ss - 0.5;
        double i0 = floor(x);
        double tt = x - i0;
        double wd[4] = {cc2d(tt + 1.0), cc1d(tt), cc1d(1.0 - tt), cc2d(2.0 - tt)};
        int ib = (int)i0;

        float acc0 = 0.f, acc1 = 0.f, acc2 = 0.f, acc3 = 0.f;
#pragma unroll
        for (int k = 0; k < 4; k++) {
            int col = ib - 1 + k;
            if (col < 0) col = 0;
            if (col > SZ - 1) col = SZ - 1;
            float wf = (float)wd[k];
            float4 cv = *reinterpret_cast<const float4*>(&c[cur][col][0]);
            acc0 += wf * cv.x;
            acc1 += wf * cv.y;
            acc2 += wf * cv.z;
            acc3 += wf * cv.w;
        }
        c[cur ^ 1][o][0] = acc0;
        c[cur ^ 1][o][1] = acc1;
        c[cur ^ 1][o][2] = acc2;
        c[cur ^ 1][o][3] = acc3;
        __syncthreads();
        cur ^= 1;
    }
}

// ---------------------------------------------------------------------------
// GEMM: 128x128 CTA tile, 8 warps (32x64 warp tiles), K-chunk 32,
// double-buffered smem. Per-buffer layout (80B row pitch):
//   Ah +0 (pitched 10240), Al +10240, Bh +20480 ; stride 30720 ; x2.
// ---------------------------------------------------------------------------
static constexpr int SMEM_BYTES = 61440;
static constexpr uint32_t T_AL = 10240;
static constexpr uint32_t T_B  = 20480;
static constexpr uint32_t BUFSTRIDE = 30720;

__device__ __forceinline__ uint32_t smem_to_u32(const void* p) {
    uint32_t a;
    asm("{ .reg .u64 t; cvta.to.shared.u64 t, %1; cvt.u32.u64 %0, t; }"
        : "=r"(a) : "l"(p));
    return a;
}
__device__ __forceinline__ void ldsm_x4(uint32_t r[4], uint32_t addr) {
    asm volatile("ldmatrix.sync.aligned.m8n8.x4.shared.b16 {%0,%1,%2,%3}, [%4];"
                 : "=r"(r[0]), "=r"(r[1]), "=r"(r[2]), "=r"(r[3]) : "r"(addr));
}
__device__ __forceinline__ void mma16816(float d[4], const uint32_t a[4],
                                         const uint32_t b[2]) {
    asm volatile(
        "mma.sync.aligned.m16n8k16.row.col.f32.f16.f16.f32 "
        "{%0,%1,%2,%3}, {%4,%5,%6,%7}, {%8,%9}, {%0,%1,%2,%3};"
        : "+f"(d[0]), "+f"(d[1]), "+f"(d[2]), "+f"(d[3])
        : "r"(a[0]), "r"(a[1]), "r"(a[2]), "r"(a[3]), "r"(b[0]), "r"(b[1]));
}
__device__ __forceinline__ void cp16(uint32_t d, const void* g) {
    asm volatile("cp.async.cg.shared.global [%0], [%1], 16;"
                 :: "r"(d), "l"(g) : "memory");
}
#define CP_COMMIT() asm volatile("cp.async.commit_group;" ::: "memory")
#define CP_WAIT(N)  asm volatile("cp.async.wait_group %0;" :: "n"(N) : "memory")

#define STS128(r0, r1, r2, r3, addr) \
    asm volatile("st.shared.v4.b32 [%0], {%1, %2, %3, %4};" \
        :: "r"(addr), "r"(r0), "r"(r1), "r"(r2), "r"(r3) : "memory")

// pack 8 floats to fp16 hi only
__device__ __forceinline__ void pack8_hi(const float v[8], uint32_t hi[4]) {
#pragma unroll
    for (int i = 0; i < 4; i++) {
        __half2 h = __halves2half2(__float2half_rn(v[2 * i]),
                                   __float2half_rn(v[2 * i + 1]));
        hi[i] = *reinterpret_cast<const uint32_t*>(&h);
    }
}

// stage A tile (128 rows x 32 k) hi+lo from pre-split gmem via cp.async
__device__ __forceinline__ void stageA_cp(uint32_t buf,
                                          const __half* __restrict__ Ah,
                                          const __half* __restrict__ Al,
                                          int mb, int kc, int tid) {
    int r = tid >> 1;                 // 0..127
    int s = (tid & 1) * 2;            // chunk 0 or 2
    uint32_t dst = buf + (uint32_t)(r * 80 + s * 16);
    size_t goff = (size_t)(mb + r) * SZ + kc + s * 8;
    cp16(dst,               Ah + goff);
    cp16(dst + 16,          Ah + goff + 8);
    cp16(dst + T_AL,        Al + goff);
    cp16(dst + T_AL + 16,   Al + goff + 8);
}

// stage B tile (128 n-rows x 32 k) hi-only from pre-split gmem via cp.async
__device__ __forceinline__ void stageB_cp(uint32_t buf,
                                          const __half* __restrict__ Bh,
                                          int nb, int kc, int tid) {
    int r = tid >> 1;
    int s = (tid & 1) * 2;
    uint32_t dst = buf + T_B + (uint32_t)(r * 80 + s * 16);
    size_t goff = (size_t)(nb + r) * SZ + kc + s * 8;
    cp16(dst,      Bh + goff);
    cp16(dst + 16, Bh + goff + 8);
}

// stage B tile from fp32 X with transpose: B[n][k] = X[kc+k][nb+n], hi-only
__device__ __forceinline__ void stageB_trans(uint32_t buf,
                                             const float* __restrict__ X,
                                             int nb, int kc, int wid, int lane) {
#pragma unroll
    for (int rep = 0; rep < 2; rep++) {
        int it = wid + rep * 8;        // 16 tasks
        int j0 = (it & 3) * 8;         // k-group of 8
        int n0 = (it >> 2) * 32;       // n-group of 32
        const float* xp = X + (size_t)(kc + j0) * SZ + nb + n0 + lane;
        float v[8];
#pragma unroll
        for (int j = 0; j < 8; j++) v[j] = xp[(size_t)j * SZ];
        uint32_t hi[4];
        pack8_hi(v, hi);
        uint32_t addr = buf + T_B +
            (uint32_t)((n0 + lane) * 80 + (j0 >> 3) * 16);
        STS128(hi[0], hi[1], hi[2], hi[3], addr);
    }
}

__device__ __forceinline__ void compute_chunk(uint32_t buf, int warpm, int warpn,
                                              int lane, float acc[2][8][4]) {
    const uint32_t arow = buf +
        (uint32_t)((warpm * 32 + (lane & 15)) * 80 + ((lane & 16) ? 16 : 0));
    const uint32_t brow = buf + T_B +
        (uint32_t)((warpn * 64 + (lane & 7) + ((lane & 16) ? 8 : 0)) * 80 +
                   ((lane & 8) ? 16 : 0));
#pragma unroll
    for (int K16 = 0; K16 < 2; K16++) {
        uint32_t aH[2][4], aL[2][4];
#pragma unroll
        for (int mt = 0; mt < 2; mt++) {
            uint32_t a = arow + (uint32_t)(mt * 16 * 80 + K16 * 32);
            ldsm_x4(aH[mt], a);
            ldsm_x4(aL[mt], a + T_AL);
        }
        uint32_t bH[4][4];
#pragma unroll
        for (int g = 0; g < 4; g++)
            ldsm_x4(bH[g], brow + (uint32_t)(g * 16 * 80 + K16 * 32));
        // term-major ordering: all Ah mmas, then all Al mmas (long RAW gaps)
#pragma unroll
        for (int g = 0; g < 4; g++)
#pragma unroll
            for (int mt = 0; mt < 2; mt++) {
                mma16816(acc[mt][2 * g],     aH[mt], bH[g]);
                mma16816(acc[mt][2 * g + 1], aH[mt], bH[g] + 2);
            }
#pragma unroll
        for (int g = 0; g < 4; g++)
#pragma unroll
            for (int mt = 0; mt < 2; mt++) {
                mma16816(acc[mt][2 * g],     aL[mt], bH[g]);
                mma16816(acc[mt][2 * g + 1], aL[mt], bH[g] + 2);
            }
    }
}

// PH1: A = C split (cp.async), B = X transposed inline; epilogue splits Y.
// PH2: A = Y split (cp.async), B = Ch (cp.async); epilogue fp32.
template <bool PH1>
__device__ __forceinline__ void mm_core(
    const __half* __restrict__ Ah, const __half* __restrict__ Al,
    const __half* __restrict__ Bh, const float* __restrict__ Xf,
    float* __restrict__ Of, __half* __restrict__ Oh, __half* __restrict__ Ol) {
    extern __shared__ char smem[];
    uint32_t sb = smem_to_u32(smem);

    const int tid   = threadIdx.x;
    const int lane  = tid & 31;
    const int wid   = tid >> 5;
    const int warpm = wid & 3;      // 4 m-tiles of 32
    const int warpn = wid >> 2;     // 2 n-tiles of 64
    const int mb    = blockIdx.y * 128;
    const int nb    = blockIdx.x * 128;

    float acc[2][8][4];
#pragma unroll
    for (int i = 0; i < 2; i++)
#pragma unroll
        for (int j = 0; j < 8; j++)
#pragma unroll
            for (int q = 0; q < 4; q++) acc[i][j][q] = 0.0f;

    // prologue: stage chunks 0,1
    stageA_cp(sb, Ah, Al, mb, 0, tid);
    if (PH1) stageB_trans(sb, Xf, nb, 0, wid, lane);
    else     stageB_cp(sb, Bh, nb, 0, tid);
    CP_COMMIT();
    stageA_cp(sb + BUFSTRIDE, Ah, Al, mb, 32, tid);
    if (PH1) stageB_trans(sb + BUFSTRIDE, Xf, nb, 32, wid, lane);
    else     stageB_cp(sb + BUFSTRIDE, Bh, nb, 32, tid);
    CP_COMMIT();

#pragma unroll 1
    for (int c = 0; c < 8; c++) {
        if (c < 7) { CP_WAIT(1); } else { CP_WAIT(0); }
        __syncthreads();
        uint32_t buf = sb + (uint32_t)((c & 1) * BUFSTRIDE);
        compute_chunk(buf, warpm, warpn, lane, acc);
        __syncthreads();
        if (c + 2 < 8) {
            stageA_cp(buf, Ah, Al, mb, (c + 2) * 32, tid);
            if (PH1) stageB_trans(buf, Xf, nb, (c + 2) * 32, wid, lane);
            else     stageB_cp(buf, Bh, nb, (c + 2) * 32, tid);
            CP_COMMIT();
        }
    }

    // epilogue
    const int rbase = mb + warpm * 32 + (lane >> 2);
    const int cbase = nb + warpn * 64 + (lane & 3) * 2;
#pragma unroll
    for (int mt = 0; mt < 2; mt++) {
#pragma unroll
        for (int nt = 0; nt < 8; nt++) {
            int col = cbase + nt * 8;
            int r0 = rbase + mt * 16;
            int r1 = r0 + 8;
            float v0 = acc[mt][nt][0], v1 = acc[mt][nt][1];
            float v2 = acc[mt][nt][2], v3 = acc[mt][nt][3];
            if (PH1) {
                __half h0 = __float2half_rn(v0), h1 = __float2half_rn(v1);
                __half h2 = __float2half_rn(v2), h3 = __float2half_rn(v3);
                __half l0 = __float2half_rn(v0 - __half2float(h0));
                __half l1 = __float2half_rn(v1 - __half2float(h1));
                __half l2 = __float2half_rn(v2 - __half2float(h2));
                __half l3 = __float2half_rn(v3 - __half2float(h3));
                *reinterpret_cast<__half2*>(Oh + (size_t)r0 * SZ + col) =
                    __halves2half2(h0, h1);
                *reinterpret_cast<__half2*>(Ol + (size_t)r0 * SZ + col) =
                    __halves2half2(l0, l1);
                *reinterpret_cast<__half2*>(Oh + (size_t)r1 * SZ + col) =
                    __halves2half2(h2, h3);
                *reinterpret_cast<__half2*>(Ol + (size_t)r1 * SZ + col) =
                    __halves2half2(l2, l3);
            } else {
                *reinterpret_cast<float2*>(Of + (size_t)r0 * SZ + col) =
                    make_float2(v0, v1);
                *reinterpret_cast<float2*>(Of + (size_t)r1 * SZ + col) =
                    make_float2(v2, v3);
            }
        }
    }
}

__global__ void __launch_bounds__(256, 2)
phase1_kernel(const float* __restrict__ x0, const int* __restrict__ t) {
    int img = blockIdx.z;
    int tb  = __ldg(&t[img / 3]);
    size_t io = (size_t)img * SZ * SZ;
    mm_core<true>(&g_Ch[tb][0][0], &g_Cl[tb][0][0], nullptr,
                  x0 + io, nullptr, g_Yh + io, g_Yl + io);
}

__global__ void __launch_bounds__(256, 2)
phase2_kernel(float* __restrict__ out, const int* __restrict__ t) {
    int img = blockIdx.z;
    int tb  = __ldg(&t[img / 3]);
    size_t io = (size_t)img * SZ * SZ;
    mm_core<false>(g_Yh + io, g_Yl + io, &g_Ch[tb][0][0],
                   nullptr, out + io, nullptr, nullptr);
}

// ---------------------------------------------------------------------------
extern "C" void kernel_launch(void* const* d_in, const int* in_sizes, int n_in,
                              void* d_out, int out_size) {
    const float* x0 = (const float*)d_in[0];
    const int*   t  = (const int*)d_in[1];
    float* out      = (float*)d_out;

    chain_kernel<<<SZ / 4, 256>>>();

    cudaFuncSetAttribute(phase1_kernel,
                         cudaFuncAttributeMaxDynamicSharedMemorySize, SMEM_BYTES);
    cudaFuncSetAttribute(phase2_kernel,
                         cudaFuncAttributeMaxDynamicSharedMemorySize, SMEM_BYTES);
    phase1_kernel<<<dim3(2, 2, NIMG), 256, SMEM_BYTES>>>(x0, t);
    phase2_kernel<<<dim3(2, 2, NIMG), 256, SMEM_BYTES>>>(out, t);
}

// round 10
// speedup vs baseline: 2.2871x; 1.2398x over previous
#include <cuda_runtime.h>
#include <cuda_fp16.h>
#include <math.h>
#include <stdint.h>

// ===========================================================================
// PixelateDegradation:  out[b,c] = C_{t[b]} @ x0[b,c] @ C_{t[b]}^T
// mma.sync tensor path, 2-term fp16 split:  D = (Ah + Al) @ Bh
// R10: fp64 bicubic taps hoisted to a tiny parallel taps_kernel; chain step
// body is now 4 cached-float FMAs + barrier.
// ===========================================================================

#define TS 20
#define SZ 256
#define NIMG 192

__device__ __half g_Ch[TS][SZ][SZ];
__device__ __half g_Cl[TS][SZ][SZ];
__device__ __half g_Yh[(size_t)NIMG * SZ * SZ];   // Y = C@X hi (m-major, k-contig)
__device__ __half g_Yl[(size_t)NIMG * SZ * SZ];   // Y lo
__device__ float  g_w[TS][SZ][4];                 // tap weights (steps 0..TS-2)
__device__ int    g_ib[TS][SZ];                   // tap base index

// ---------------------------------------------------------------------------
// taps_kernel: one thread per (step s, row o). fp64 to match numpy build.
// ---------------------------------------------------------------------------
__device__ __forceinline__ double cc1d(double x) {
    const double A = -0.75;
    return ((A + 2.0) * x - (A + 3.0)) * x * x + 1.0;
}
__device__ __forceinline__ double cc2d(double x) {
    const double A = -0.75;
    return ((A * x - 5.0 * A) * x + 8.0 * A) * x - 4.0 * A;
}

__global__ void taps_kernel() {
    int s = blockIdx.x;      // 0..TS-2
    int o = threadIdx.x;

    double ss = (double)(SZ - s);
    int src = (int)floor((o + 0.5) * ss / 256.0);
    int smax = (SZ - s) - 1;
    if (src > smax) src = smax;
    if (src < 0) src = 0;
    double x  = (src + 0.5) * 256.0 / ss - 0.5;
    double i0 = floor(x);
    double tt = x - i0;
    g_w[s][o][0] = (float)cc2d(tt + 1.0);
    g_w[s][o][1] = (float)cc1d(tt);
    g_w[s][o][2] = (float)cc1d(1.0 - tt);
    g_w[s][o][3] = (float)cc2d(2.0 - tt);
    g_ib[s][o]   = (int)i0 - 1;
}

// ---------------------------------------------------------------------------
// chain_kernel: block = 4 columns of C, thread = row o. 20 sequential steps,
// taps read from g_w/g_ib (L2-cached after first block).
// ---------------------------------------------------------------------------
__global__ void chain_kernel() {
    const int o  = threadIdx.x;
    const int h0 = blockIdx.x * 4;

    __shared__ float c[2][SZ][4];
#pragma unroll
    for (int j = 0; j < 4; j++)
        c[0][o][j] = (o == h0 + j) ? 1.0f : 0.0f;
    __syncthreads();

    int cur = 0;
#pragma unroll 1
    for (int s = 0; s < TS; s++) {
        // store C_s column slice (own row of shared -> no sync needed)
        float4 v = *reinterpret_cast<const float4*>(&c[cur][o][0]);
        __half hx = __float2half_rn(v.x), hy = __float2half_rn(v.y);
        __half hz = __float2half_rn(v.z), hw = __float2half_rn(v.w);
        __half lx = __float2half_rn(v.x - __half2float(hx));
        __half ly = __float2half_rn(v.y - __half2float(hy));
        __half lz = __float2half_rn(v.z - __half2float(hz));
        __half lw = __float2half_rn(v.w - __half2float(hw));
        uint2 hs, ls;
        __half2 t0 = __halves2half2(hx, hy), t1 = __halves2half2(hz, hw);
        hs.x = *reinterpret_cast<uint32_t*>(&t0);
        hs.y = *reinterpret_cast<uint32_t*>(&t1);
        __half2 t2 = __halves2half2(lx, ly), t3 = __halves2half2(lz, lw);
        ls.x = *reinterpret_cast<uint32_t*>(&t2);
        ls.y = *reinterpret_cast<uint32_t*>(&t3);
        *reinterpret_cast<uint2*>(&g_Ch[s][o][h0]) = hs;
        *reinterpret_cast<uint2*>(&g_Cl[s][o][h0]) = ls;

        if (s == TS - 1) break;

        float4 w = *reinterpret_cast<const float4*>(&g_w[s][o][0]);
        int ib = g_ib[s][o];
        float wf[4] = {w.x, w.y, w.z, w.w};

        float acc0 = 0.f, acc1 = 0.f, acc2 = 0.f, acc3 = 0.f;
#pragma unroll
        for (int k = 0; k < 4; k++) {
            int col = ib + k;
            if (col < 0) col = 0;
            if (col > SZ - 1) col = SZ - 1;
            float4 cv = *reinterpret_cast<const float4*>(&c[cur][col][0]);
            acc0 += wf[k] * cv.x;
            acc1 += wf[k] * cv.y;
            acc2 += wf[k] * cv.z;
            acc3 += wf[k] * cv.w;
        }
        c[cur ^ 1][o][0] = acc0;
        c[cur ^ 1][o][1] = acc1;
        c[cur ^ 1][o][2] = acc2;
        c[cur ^ 1][o][3] = acc3;
        __syncthreads();
        cur ^= 1;
    }
}

// ---------------------------------------------------------------------------
// GEMM: 128x128 CTA tile, 8 warps (32x64 warp tiles), K-chunk 32,
// double-buffered smem. Per-buffer layout (80B row pitch):
//   Ah +0 (pitched 10240), Al +10240, Bh +20480 ; stride 30720 ; x2.
// ---------------------------------------------------------------------------
static constexpr int SMEM_BYTES = 61440;
static constexpr uint32_t T_AL = 10240;
static constexpr uint32_t T_B  = 20480;
static constexpr uint32_t BUFSTRIDE = 30720;

__device__ __forceinline__ uint32_t smem_to_u32(const void* p) {
    uint32_t a;
    asm("{ .reg .u64 t; cvta.to.shared.u64 t, %1; cvt.u32.u64 %0, t; }"
        : "=r"(a) : "l"(p));
    return a;
}
__device__ __forceinline__ void ldsm_x4(uint32_t r[4], uint32_t addr) {
    asm volatile("ldmatrix.sync.aligned.m8n8.x4.shared.b16 {%0,%1,%2,%3}, [%4];"
                 : "=r"(r[0]), "=r"(r[1]), "=r"(r[2]), "=r"(r[3]) : "r"(addr));
}
__device__ __forceinline__ void mma16816(float d[4], const uint32_t a[4],
                                         const uint32_t b[2]) {
    asm volatile(
        "mma.sync.aligned.m16n8k16.row.col.f32.f16.f16.f32 "
        "{%0,%1,%2,%3}, {%4,%5,%6,%7}, {%8,%9}, {%0,%1,%2,%3};"
        : "+f"(d[0]), "+f"(d[1]), "+f"(d[2]), "+f"(d[3])
        : "r"(a[0]), "r"(a[1]), "r"(a[2]), "r"(a[3]), "r"(b[0]), "r"(b[1]));
}
__device__ __forceinline__ void cp16(uint32_t d, const void* g) {
    asm volatile("cp.async.cg.shared.global [%0], [%1], 16;"
                 :: "r"(d), "l"(g) : "memory");
}
#define CP_COMMIT() asm volatile("cp.async.commit_group;" ::: "memory")
#define CP_WAIT(N)  asm volatile("cp.async.wait_group %0;" :: "n"(N) : "memory")

#define STS128(r0, r1, r2, r3, addr) \
    asm volatile("st.shared.v4.b32 [%0], {%1, %2, %3, %4};" \
        :: "r"(addr), "r"(r0), "r"(r1), "r"(r2), "r"(r3) : "memory")

// pack 8 floats to fp16 hi only
__device__ __forceinline__ void pack8_hi(const float v[8], uint32_t hi[4]) {
#pragma unroll
    for (int i = 0; i < 4; i++) {
        __half2 h = __halves2half2(__float2half_rn(v[2 * i]),
                                   __float2half_rn(v[2 * i + 1]));
        hi[i] = *reinterpret_cast<const uint32_t*>(&h);
    }
}

// stage A tile (128 rows x 32 k) hi+lo from pre-split gmem via cp.async
__device__ __forceinline__ void stageA_cp(uint32_t buf,
                                          const __half* __restrict__ Ah,
                                          const __half* __restrict__ Al,
                                          int mb, int kc, int tid) {
    int r = tid >> 1;                 // 0..127
    int s = (tid & 1) * 2;            // chunk 0 or 2
    uint32_t dst = buf + (uint32_t)(r * 80 + s * 16);
    size_t goff = (size_t)(mb + r) * SZ + kc + s * 8;
    cp16(dst,               Ah + goff);
    cp16(dst + 16,          Ah + goff + 8);
    cp16(dst + T_AL,        Al + goff);
    cp16(dst + T_AL + 16,   Al + goff + 8);
}

// stage B tile (128 n-rows x 32 k) hi-only from pre-split gmem via cp.async
__device__ __forceinline__ void stageB_cp(uint32_t buf,
                                          const __half* __restrict__ Bh,
                                          int nb, int kc, int tid) {
    int r = tid >> 1;
    int s = (tid & 1) * 2;
    uint32_t dst = buf + T_B + (uint32_t)(r * 80 + s * 16);
    size_t goff = (size_t)(nb + r) * SZ + kc + s * 8;
    cp16(dst,      Bh + goff);
    cp16(dst + 16, Bh + goff + 8);
}

// stage B tile from fp32 X with transpose: B[n][k] = X[kc+k][nb+n], hi-only
__device__ __forceinline__ void stageB_trans(uint32_t buf,
                                             const float* __restrict__ X,
                                             int nb, int kc, int wid, int lane) {
#pragma unroll
    for (int rep = 0; rep < 2; rep++) {
        int it = wid + rep * 8;        // 16 tasks
        int j0 = (it & 3) * 8;         // k-group of 8
        int n0 = (it >> 2) * 32;       // n-group of 32
        const float* xp = X + (size_t)(kc + j0) * SZ + nb + n0 + lane;
        float v[8];
#pragma unroll
        for (int j = 0; j < 8; j++) v[j] = xp[(size_t)j * SZ];
        uint32_t hi[4];
        pack8_hi(v, hi);
        uint32_t addr = buf + T_B +
            (uint32_t)((n0 + lane) * 80 + (j0 >> 3) * 16);
        STS128(hi[0], hi[1], hi[2], hi[3], addr);
    }
}

__device__ __forceinline__ void compute_chunk(uint32_t buf, int warpm, int warpn,
                                              int lane, float acc[2][8][4]) {
    const uint32_t arow = buf +
        (uint32_t)((warpm * 32 + (lane & 15)) * 80 + ((lane & 16) ? 16 : 0));
    const uint32_t brow = buf + T_B +
        (uint32_t)((warpn * 64 + (lane & 7) + ((lane & 16) ? 8 : 0)) * 80 +
                   ((lane & 8) ? 16 : 0));
#pragma unroll
    for (int K16 = 0; K16 < 2; K16++) {
        uint32_t aH[2][4], aL[2][4];
#pragma unroll
        for (int mt = 0; mt < 2; mt++) {
            uint32_t a = arow + (uint32_t)(mt * 16 * 80 + K16 * 32);
            ldsm_x4(aH[mt], a);
            ldsm_x4(aL[mt], a + T_AL);
        }
        uint32_t bH[4][4];
#pragma unroll
        for (int g = 0; g < 4; g++)
            ldsm_x4(bH[g], brow + (uint32_t)(g * 16 * 80 + K16 * 32));
        // term-major ordering: all Ah mmas, then all Al mmas (long RAW gaps)
#pragma unroll
        for (int g = 0; g < 4; g++)
#pragma unroll
            for (int mt = 0; mt < 2; mt++) {
                mma16816(acc[mt][2 * g],     aH[mt], bH[g]);
                mma16816(acc[mt][2 * g + 1], aH[mt], bH[g] + 2);
            }
#pragma unroll
        for (int g = 0; g < 4; g++)
#pragma unroll
            for (int mt = 0; mt < 2; mt++) {
                mma16816(acc[mt][2 * g],     aL[mt], bH[g]);
                mma16816(acc[mt][2 * g + 1], aL[mt], bH[g] + 2);
            }
    }
}

// PH1: A = C split (cp.async), B = X transposed inline; epilogue splits Y.
// PH2: A = Y split (cp.async), B = Ch (cp.async); epilogue fp32.
template <bool PH1>
__device__ __forceinline__ void mm_core(
    const __half* __restrict__ Ah, const __half* __restrict__ Al,
    const __half* __restrict__ Bh, const float* __restrict__ Xf,
    float* __restrict__ Of, __half* __restrict__ Oh, __half* __restrict__ Ol) {
    extern __shared__ char smem[];
    uint32_t sb = smem_to_u32(smem);

    const int tid   = threadIdx.x;
    const int lane  = tid & 31;
    const int wid   = tid >> 5;
    const int warpm = wid & 3;      // 4 m-tiles of 32
    const int warpn = wid >> 2;     // 2 n-tiles of 64
    const int mb    = blockIdx.y * 128;
    const int nb    = blockIdx.x * 128;

    float acc[2][8][4];
#pragma unroll
    for (int i = 0; i < 2; i++)
#pragma unroll
        for (int j = 0; j < 8; j++)
#pragma unroll
            for (int q = 0; q < 4; q++) acc[i][j][q] = 0.0f;

    // prologue: stage chunks 0,1
    stageA_cp(sb, Ah, Al, mb, 0, tid);
    if (PH1) stageB_trans(sb, Xf, nb, 0, wid, lane);
    else     stageB_cp(sb, Bh, nb, 0, tid);
    CP_COMMIT();
    stageA_cp(sb + BUFSTRIDE, Ah, Al, mb, 32, tid);
    if (PH1) stageB_trans(sb + BUFSTRIDE, Xf, nb, 32, wid, lane);
    else     stageB_cp(sb + BUFSTRIDE, Bh, nb, 32, tid);
    CP_COMMIT();

#pragma unroll 1
    for (int c = 0; c < 8; c++) {
        if (c < 7) { CP_WAIT(1); } else { CP_WAIT(0); }
        __syncthreads();
        uint32_t buf = sb + (uint32_t)((c & 1) * BUFSTRIDE);
        compute_chunk(buf, warpm, warpn, lane, acc);
        __syncthreads();
        if (c + 2 < 8) {
            stageA_cp(buf, Ah, Al, mb, (c + 2) * 32, tid);
            if (PH1) stageB_trans(buf, Xf, nb, (c + 2) * 32, wid, lane);
            else     stageB_cp(buf, Bh, nb, (c + 2) * 32, tid);
            CP_COMMIT();
        }
    }

    // epilogue
    const int rbase = mb + warpm * 32 + (lane >> 2);
    const int cbase = nb + warpn * 64 + (lane & 3) * 2;
#pragma unroll
    for (int mt = 0; mt < 2; mt++) {
#pragma unroll
        for (int nt = 0; nt < 8; nt++) {
            int col = cbase + nt * 8;
            int r0 = rbase + mt * 16;
            int r1 = r0 + 8;
            float v0 = acc[mt][nt][0], v1 = acc[mt][nt][1];
            float v2 = acc[mt][nt][2], v3 = acc[mt][nt][3];
            if (PH1) {
                __half h0 = __float2half_rn(v0), h1 = __float2half_rn(v1);
                __half h2 = __float2half_rn(v2), h3 = __float2half_rn(v3);
                __half l0 = __float2half_rn(v0 - __half2float(h0));
                __half l1 = __float2half_rn(v1 - __half2float(h1));
                __half l2 = __float2half_rn(v2 - __half2float(h2));
                __half l3 = __float2half_rn(v3 - __half2float(h3));
                *reinterpret_cast<__half2*>(Oh + (size_t)r0 * SZ + col) =
                    __halves2half2(h0, h1);
                *reinterpret_cast<__half2*>(Ol + (size_t)r0 * SZ + col) =
                    __halves2half2(l0, l1);
                *reinterpret_cast<__half2*>(Oh + (size_t)r1 * SZ + col) =
                    __halves2half2(h2, h3);
                *reinterpret_cast<__half2*>(Ol + (size_t)r1 * SZ + col) =
                    __halves2half2(l2, l3);
            } else {
                *reinterpret_cast<float2*>(Of + (size_t)r0 * SZ + col) =
                    make_float2(v0, v1);
                *reinterpret_cast<float2*>(Of + (size_t)r1 * SZ + col) =
                    make_float2(v2, v3);
            }
        }
    }
}

__global__ void __launch_bounds__(256, 2)
phase1_kernel(const float* __restrict__ x0, const int* __restrict__ t) {
    int img = blockIdx.z;
    int tb  = __ldg(&t[img / 3]);
    size_t io = (size_t)img * SZ * SZ;
    mm_core<true>(&g_Ch[tb][0][0], &g_Cl[tb][0][0], nullptr,
                  x0 + io, nullptr, g_Yh + io, g_Yl + io);
}

__global__ void __launch_bounds__(256, 2)
phase2_kernel(float* __restrict__ out, const int* __restrict__ t) {
    int img = blockIdx.z;
    int tb  = __ldg(&t[img / 3]);
    size_t io = (size_t)img * SZ * SZ;
    mm_core<false>(g_Yh + io, g_Yl + io, &g_Ch[tb][0][0],
                   nullptr, out + io, nullptr, nullptr);
}

// ---------------------------------------------------------------------------
extern "C" void kernel_launch(void* const* d_in, const int* in_sizes, int n_in,
                              void* d_out, int out_size) {
    const float* x0 = (const float*)d_in[0];
    const int*   t  = (const int*)d_in[1];
    float* out      = (float*)d_out;

    taps_kernel<<<TS - 1, 256>>>();
    chain_kernel<<<SZ / 4, 256>>>();

    cudaFuncSetAttribute(phase1_kernel,
                         cudaFuncAttributeMaxDynamicSharedMemorySize, SMEM_BYTES);
    cudaFuncSetAttribute(phase2_kernel,
                         cudaFuncAttributeMaxDynamicSharedMemorySize, SMEM_BYTES);
    phase1_kernel<<<dim3(2, 2, NIMG), 256, SMEM_BYTES>>>(x0, t);
    phase2_kernel<<<dim3(2, 2, NIMG), 256, SMEM_BYTES>>>(out, t);
}